// round 7
// baseline (speedup 1.0000x reference)
#include <cuda_runtime.h>
#include <math.h>
#include <stdint.h>
#include <stddef.h>

// ---------------- problem constants ----------------
#define Bn   32
#define Tn   1024
#define Dn   1024
#define Sn   256
#define KF   3
#define Mrows (Bn*Tn)                 // 32768
#define IOFF  ((size_t)Bn*Tn*Dn)      // 33554432 (indices start in d_out)
#define LOFF  (IOFF + (size_t)Bn*Tn)  // total scalar slot

#define GRU_CTAS    148
#define GRU_WARPS   7
#define GRU_THREADS (GRU_WARPS*32)    // 224
#define HS_PITCH    1028              // 1028 % 32 == 4 -> conflict-free LDS.128
#define GRU_SMEM    (32*HS_PITCH*4 + 32*4)

// ---------------- device scratch (no allocations) ----------------
__device__ float g_dots[(size_t)Mrows * Sn];   // 33.5 MB : 2*F.C^T
__device__ float g_H  [(size_t)Mrows * Dn];    // 134 MB, row = t*Bn + b
__device__ float g_Hp [(size_t)Mrows * Dn];    // 134 MB, same layout
__device__ float g_GI [(size_t)Sn * 3*Dn];     // 3 MB
__device__ float g_hT [2][Bn * Dn];            // double-buffered h, [b][k]
__device__ float g_rnorm[Mrows];
__device__ float g_cnorm[Sn];
__device__ float g_zbias[Sn];                  // zero-initialized, never written
__device__ int   g_idx[Mrows];                 // row = b*Tn + t
__device__ float g_mse_arr[Mrows/8];           // 4096 per-block partials
__device__ float g_cp_arr[KF*(Tn-1)];          // 3069 slots
__device__ unsigned g_bar;

// ---------------- init ----------------
__global__ void init_kernel() {
    int i = blockIdx.x * 256 + threadIdx.x;
    if (i < Bn*Dn) g_hT[0][i] = 0.f;
    if (i == 0) g_bar = 0u;
}

// ---------------- row squared norms (8 rows/block, warp per row) -------------
__global__ void rownorm_kernel(const float* __restrict__ X,
                               float* __restrict__ out, int rows) {
    int wid = threadIdx.x >> 5, lane = threadIdx.x & 31;
    int row = blockIdx.x * 8 + wid;
    if (row >= rows) return;
    const float4* x = (const float4*)(X + (size_t)row * Dn);
    float s = 0.f;
#pragma unroll
    for (int j = 0; j < 8; j++) {
        float4 v = x[j*32 + lane];
        s += v.x*v.x + v.y*v.y + v.z*v.z + v.w*v.w;
    }
#pragma unroll
    for (int off = 16; off; off >>= 1) s += __shfl_xor_sync(0xffffffffu, s, off);
    if (lane == 0) out[row] = s;
}

// ---------------- SGEMM: C = alpha*A*B^T + bias[col] -------------------------
// A: MxK row-major, B: NxK row-major, C: MxN. M,N mult of 128, K mult of 16.
__global__ __launch_bounds__(256, 2)
void sgemm_nt(const float* __restrict__ A, const float* __restrict__ Bm,
              float* __restrict__ C, const float* __restrict__ bias,
              int M, int N, int K, float alpha)
{
    __shared__ float As[16][128];
    __shared__ float Bs[16][128];
    const int tid = threadIdx.x;
    const int tx = tid & 15, ty = tid >> 4;
    const float* Ab = A + (size_t)blockIdx.y * 128 * K;
    const float* Bb = Bm + (size_t)blockIdx.x * 128 * K;

    float acc[8][8];
#pragma unroll
    for (int i = 0; i < 8; i++)
#pragma unroll
        for (int j = 0; j < 8; j++) acc[i][j] = 0.f;

    for (int kt = 0; kt < K; kt += 16) {
#pragma unroll
        for (int r = 0; r < 2; r++) {
            int f   = tid + r * 256;           // 0..511
            int row = f >> 2;                  // 0..127
            int c4  = (f & 3) << 2;            // 0,4,8,12
            float4 va = *(const float4*)(Ab + (size_t)row * K + kt + c4);
            As[c4+0][row] = va.x; As[c4+1][row] = va.y;
            As[c4+2][row] = va.z; As[c4+3][row] = va.w;
            float4 vb = *(const float4*)(Bb + (size_t)row * K + kt + c4);
            Bs[c4+0][row] = vb.x; Bs[c4+1][row] = vb.y;
            Bs[c4+2][row] = vb.z; Bs[c4+3][row] = vb.w;
        }
        __syncthreads();
#pragma unroll
        for (int kk = 0; kk < 16; kk++) {
            float a[8], b[8];
            *(float4*)&a[0] = *(const float4*)&As[kk][ty*8];
            *(float4*)&a[4] = *(const float4*)&As[kk][ty*8+4];
            *(float4*)&b[0] = *(const float4*)&Bs[kk][tx*8];
            *(float4*)&b[4] = *(const float4*)&Bs[kk][tx*8+4];
#pragma unroll
            for (int i = 0; i < 8; i++)
#pragma unroll
                for (int j = 0; j < 8; j++) acc[i][j] += a[i] * b[j];
        }
        __syncthreads();
    }
#pragma unroll
    for (int i = 0; i < 8; i++) {
        size_t row = (size_t)blockIdx.y * 128 + ty*8 + i;
#pragma unroll
        for (int j = 0; j < 8; j += 4) {
            int col = blockIdx.x * 128 + tx*8 + j;
            float4 o;
            o.x = alpha * acc[i][j+0] + bias[col+0];
            o.y = alpha * acc[i][j+1] + bias[col+1];
            o.z = alpha * acc[i][j+2] + bias[col+2];
            o.w = alpha * acc[i][j+3] + bias[col+3];
            *(float4*)(C + row * (size_t)N + col) = o;
        }
    }
}

// ---------------- argmin (reference-exact rounding) + gather + mse -----------
// Reference: d2 = (||f||^2 - 2 f.C^T) + ||c||^2, each op f32-rounded.
// The (A-B) rounding quantizes to the absolute 2^-13 grid at |x|~1024, creating
// ties that jnp.argmin resolves by FIRST index. We replicate that exactly.
__global__ void argmin_kernel(const float* __restrict__ codebook,
                              float* __restrict__ dout) {
    int wid = threadIdx.x >> 5, lane = threadIdx.x & 31;
    int row = blockIdx.x * 8 + wid;
    __shared__ float part[8];
    __shared__ float cn_s[Sn];
    if (threadIdx.x < Sn) cn_s[threadIdx.x] = g_cnorm[threadIdx.x];
    __syncthreads();

    const float rn = g_rnorm[row];
    float bv = 3.4e38f; int bi = 0;
#pragma unroll
    for (int j = 0; j < 8; j++) {
        int i = j * 32 + lane;                   // ascending per lane
        float dot2 = g_dots[(size_t)row * Sn + i];        // = 2 * f.c_i
        float v = __fadd_rn(__fsub_rn(rn, dot2), cn_s[i]); // (A-B)+C, no FMA
        if (v < bv) { bv = v; bi = i; }          // first min per lane
    }
#pragma unroll
    for (int off = 16; off; off >>= 1) {
        float ov = __shfl_xor_sync(0xffffffffu, bv, off);
        int   oi = __shfl_xor_sync(0xffffffffu, bi, off);
        if (ov < bv || (ov == bv && oi < bi)) { bv = ov; bi = oi; }
    }
    if (lane == 0) {
        g_idx[row] = bi;
        dout[IOFF + row] = (float)bi;
        part[wid] = bv;                          // ||f - c*||^2 (quantized)
    }
    // gather quantized row (bi identical across lanes after reduction)
    const float4* c4 = (const float4*)(codebook + (size_t)bi * Dn);
    float4* o4 = (float4*)(dout + (size_t)row * Dn);
#pragma unroll
    for (int j = 0; j < 8; j++) o4[j*32 + lane] = __ldg(c4 + j*32 + lane);

    __syncthreads();
    if (threadIdx.x == 0) {
        float s = 0.f;
#pragma unroll
        for (int w = 0; w < 8; w++) s += part[w];
        g_mse_arr[blockIdx.x] = s;
    }
}

// ---------------- persistent GRU recurrence ----------------------------------
__device__ __forceinline__ unsigned ld_acquire_u32(const unsigned* p) {
    unsigned v;
    asm volatile("ld.acquire.gpu.u32 %0, [%1];" : "=r"(v) : "l"(p) : "memory");
    return v;
}

__global__ __launch_bounds__(GRU_THREADS, 1)
void gru_kernel(const float* __restrict__ W_hh, const float* __restrict__ b_hh)
{
    extern __shared__ float sh[];                 // [32][HS_PITCH] + 32 codes
    int* codes_s = (int*)(sh + 32 * HS_PITCH);
    const int tid  = threadIdx.x;
    const int wid  = tid >> 5, lane = tid & 31;
    const int d    = blockIdx.x * GRU_WARPS + wid;
    const bool active = (d < Dn);

    float bh_r = 0.f, bh_z = 0.f, bh_n = 0.f;
    const float4 *wr4 = 0, *wz4 = 0, *wn4 = 0;
    if (active) {
        bh_r = b_hh[d]; bh_z = b_hh[Dn + d]; bh_n = b_hh[2*Dn + d];
        wr4 = (const float4*)(W_hh + (size_t)d        * Dn);
        wz4 = (const float4*)(W_hh + (size_t)(Dn + d) * Dn);
        wn4 = (const float4*)(W_hh + (size_t)(2*Dn+d) * Dn);
    }

    for (int t = 0; t < Tn; t++) {
        const float4* hin4 = (const float4*)g_hT[t & 1];
        float*        hout = g_hT[(t + 1) & 1];

        // stage full h (32x1024 f32) into smem, padded [b][k]
        for (int i = tid; i < (Bn*Dn)/4; i += GRU_THREADS) {
            int b  = i >> 8;                      // 256 float4 per batch row
            int kf = i & 255;
            *(float4*)(sh + b * HS_PITCH + kf * 4) = hin4[i];
        }
        if (tid < Bn) codes_s[tid] = g_idx[tid * Tn + t];
        __syncthreads();

        if (active) {
            int code = codes_s[lane];
            const float* gi = g_GI + (size_t)code * (3*Dn);
            float gir = __ldg(gi + d);
            float giz = __ldg(gi + Dn + d);
            float gin = __ldg(gi + 2*Dn + d);

            const float4* hrow = (const float4*)(sh + lane * HS_PITCH);
            float ar = 0.f, az = 0.f, an = 0.f;
#pragma unroll 4
            for (int q = 0; q < Dn/4; q++) {
                float4 h4 = hrow[q];
                float4 w1 = __ldg(wr4 + q);
                float4 w2 = __ldg(wz4 + q);
                float4 w3 = __ldg(wn4 + q);
                ar += w1.x*h4.x + w1.y*h4.y + w1.z*h4.z + w1.w*h4.w;
                az += w2.x*h4.x + w2.y*h4.y + w2.z*h4.z + w2.w*h4.w;
                an += w3.x*h4.x + w3.y*h4.y + w3.z*h4.z + w3.w*h4.w;
            }
            float r = 1.f / (1.f + expf(-(ar + bh_r + gir)));
            float z = 1.f / (1.f + expf(-(az + bh_z + giz)));
            float n = tanhf(gin + r * (an + bh_n));
            float hprev = sh[lane * HS_PITCH + d];
            float hnew  = (1.f - z) * n + z * hprev;
            hout[lane * Dn + d] = hnew;
            g_H[((size_t)t * Bn + lane) * Dn + d] = hnew;
        }
        __threadfence();
        __syncthreads();
        if (tid == 0) {
            atomicAdd(&g_bar, 1u);
            unsigned target = (unsigned)GRU_CTAS * (unsigned)(t + 1);
            while (ld_acquire_u32(&g_bar) < target) { }
        }
        __syncthreads();
    }
}

// ---------------- CP loss per (k,t): -log(mean_b sigmoid(Hp.(fpos-fneg))) ----
__global__ void cploss_kernel(const float* __restrict__ features,
                              const int* __restrict__ neg_idx)
{
    int t  = blockIdx.x;            // 0..Tn-2
    int kf = blockIdx.y;            // 0..KF-1
    int k  = kf + 1;
    int slot = kf * (Tn - 1) + t;
    if (t >= Tn - k) { if (threadIdx.x == 0) g_cp_arr[slot] = 0.f; return; }

    __shared__ float sig_s[Bn];
    int wid = threadIdx.x >> 5, lane = threadIdx.x & 31;
#pragma unroll
    for (int bi = 0; bi < 4; bi++) {
        int b = wid * 4 + bi;
        const float4* hp = (const float4*)(g_Hp + ((size_t)t * Bn + b) * Dn);
        const float4* fp = (const float4*)(features + ((size_t)b * Tn + (t + k)) * Dn);
        int bneg = neg_idx[((size_t)kf * Tn + t) * Bn + b];
        const float4* fn = (const float4*)(features + ((size_t)bneg * Tn + t) * Dn);
        float s = 0.f;
#pragma unroll
        for (int j = 0; j < 8; j++) {
            float4 h4 = hp[j*32 + lane];
            float4 p4 = fp[j*32 + lane];
            float4 n4 = fn[j*32 + lane];
            s += h4.x*(p4.x-n4.x) + h4.y*(p4.y-n4.y)
               + h4.z*(p4.z-n4.z) + h4.w*(p4.w-n4.w);
        }
#pragma unroll
        for (int off = 16; off; off >>= 1) s += __shfl_xor_sync(0xffffffffu, s, off);
        if (lane == 0) sig_s[b] = 1.f / (1.f + expf(-s));
    }
    __syncthreads();
    if (threadIdx.x == 0) {
        float m = 0.f;
#pragma unroll
        for (int b = 0; b < Bn; b++) m += sig_s[b];
        g_cp_arr[slot] = -logf(m * (1.f / (float)Bn));
    }
}

// ---------------- final deterministic reduction -------------------------------
__global__ void finalize_kernel(float* __restrict__ dout) {
    __shared__ float red[256];
    int tid = threadIdx.x;
    float s = 0.f;
    for (int i = tid; i < KF*(Tn-1); i += 256) s += g_cp_arr[i];
    red[tid] = s; __syncthreads();
    for (int o = 128; o; o >>= 1) { if (tid < o) red[tid] += red[tid+o]; __syncthreads(); }
    float cp = red[0]; __syncthreads();
    float m = 0.f;
    for (int i = tid; i < Mrows/8; i += 256) m += g_mse_arr[i];
    red[tid] = m; __syncthreads();
    for (int o = 128; o; o >>= 1) { if (tid < o) red[tid] += red[tid+o]; __syncthreads(); }
    if (tid == 0) {
        float mse = red[0] / ((float)Mrows * (float)Dn);
        // commitment == codebook loss numerically -> 1.25 * mse
        dout[LOFF] = cp / (float)(KF * (Tn - KF)) + 1.25f * mse;
    }
}

// ---------------- launch --------------------------------------------------------
extern "C" void kernel_launch(void* const* d_in, const int* in_sizes, int n_in,
                              void* d_out, int out_size) {
    (void)in_sizes; (void)n_in; (void)out_size;
    const float* features = (const float*)d_in[0];
    const float* codebook = (const float*)d_in[1];
    const float* W_ih     = (const float*)d_in[2];
    const float* W_hh     = (const float*)d_in[3];
    const float* b_ih     = (const float*)d_in[4];
    const float* b_hh     = (const float*)d_in[5];
    const float* W_p      = (const float*)d_in[6];
    const float* b_p      = (const float*)d_in[7];
    const int*   neg_idx  = (const int*)d_in[8];
    float* dout = (float*)d_out;

    void *p_rnorm, *p_cnorm, *p_dots, *p_GI, *p_H, *p_Hp, *p_zb;
    cudaGetSymbolAddress(&p_rnorm, g_rnorm);
    cudaGetSymbolAddress(&p_cnorm, g_cnorm);
    cudaGetSymbolAddress(&p_dots,  g_dots);
    cudaGetSymbolAddress(&p_GI,    g_GI);
    cudaGetSymbolAddress(&p_H,     g_H);
    cudaGetSymbolAddress(&p_Hp,    g_Hp);
    cudaGetSymbolAddress(&p_zb,    g_zbias);

    cudaFuncSetAttribute(gru_kernel,
        cudaFuncAttributeMaxDynamicSharedMemorySize, GRU_SMEM);

    init_kernel<<<(Bn*Dn + 255)/256, 256>>>();

    rownorm_kernel<<<Mrows/8, 256>>>(features, (float*)p_rnorm, Mrows);
    rownorm_kernel<<<Sn/8,    256>>>(codebook, (float*)p_cnorm, Sn);

    // dots = 2 * F C^T   (M x S), raw (no bias) so argmin can replicate
    // the reference's (A - B) + C rounding order exactly.
    sgemm_nt<<<dim3(Sn/128, Mrows/128), 256>>>(
        features, codebook, (float*)p_dots, (const float*)p_zb,
        Mrows, Sn, Dn, 2.0f);

    argmin_kernel<<<Mrows/8, 256>>>(codebook, dout);

    // GI = codebook @ W_ih^T + b_ih   (S x 3D)
    sgemm_nt<<<dim3(3*Dn/128, Sn/128), 256>>>(
        codebook, W_ih, (float*)p_GI, b_ih, Sn, 3*Dn, Dn, 1.0f);

    gru_kernel<<<GRU_CTAS, GRU_THREADS, GRU_SMEM>>>(W_hh, b_hh);

    // Hp = H @ W_p^T + b_p   (M x D)
    sgemm_nt<<<dim3(Dn/128, Mrows/128), 256>>>(
        (const float*)p_H, W_p, (float*)p_Hp, b_p, Mrows, Dn, Dn, 1.0f);

    cploss_kernel<<<dim3(Tn-1, KF), 256>>>(features, neg_idx);

    finalize_kernel<<<1, 256>>>(dout);
}